// round 11
// baseline (speedup 1.0000x reference)
#include <cuda_runtime.h>
#include <math.h>

typedef unsigned long long u64;
typedef unsigned int u32;

#define S_LEN 512
#define B_DIM 256
#define IN_DIM 256
#define BR_DIM 128
#define H_DIM 512
#define G_DIM 2048                 // 4*H
#define M_DIM (S_LEN * B_DIM)      // 131072

// ---------------- device scratch (no allocations allowed) ----------------
// gx layout: [(t*4+g)][h:512][b:256]  (transposed, 1 GiB)
__device__ float g_gx[(size_t)M_DIM * G_DIM];
// hs0 layout: [t][h:512][b:256]  (transposed, 256 MiB) -- doubles as layer-0 h history
__device__ float g_hs0[(size_t)S_LEN * H_DIM * B_DIM];
__device__ float g_h1t[2][H_DIM * B_DIM];               // layer-1 h double buffer, [h][b]

// per-b-column barrier state: 4 columns x 32 CTAs, slots padded to 128B lines
__device__ unsigned g_colcnt[4];
__device__ volatile unsigned g_slot[4][32][32];

// ---------------- packed f32x2 + activation helpers ----------------
__device__ __forceinline__ u64 pack2(float lo, float hi) {
    u64 r; asm("mov.b64 %0, {%1, %2};" : "=l"(r) : "f"(lo), "f"(hi)); return r;
}
__device__ __forceinline__ void unpack2(u64 v, float& lo, float& hi) {
    asm("mov.b64 {%0, %1}, %2;" : "=f"(lo), "=f"(hi) : "l"(v));
}
__device__ __forceinline__ void fma2(u64& d, u64 a, u64 b) {
    asm("fma.rn.f32x2 %0, %1, %2, %0;" : "+l"(d) : "l"(a), "l"(b));
}
__device__ __forceinline__ void add2(u64& d, u64 a) {
    asm("add.rn.f32x2 %0, %0, %1;" : "+l"(d) : "l"(a));
}
__device__ __forceinline__ float fast_sigmoid(float x) { return 1.0f / (1.0f + __expf(-x)); }
__device__ __forceinline__ float fast_tanh(float x) { return 1.0f - 2.0f / (__expf(2.0f * x) + 1.0f); }

// ---------------- cp.async ----------------
__device__ __forceinline__ u32 smem_u32(const void* p) {
    return (u32)__cvta_generic_to_shared(p);
}
#define CP16(d, s)  asm volatile("cp.async.cg.shared.global [%0], [%1], 16;" :: "r"(d), "l"(s))
#define CP8(d, s)   asm volatile("cp.async.ca.shared.global [%0], [%1], 8;"  :: "r"(d), "l"(s))
#define CP4(d, s)   asm volatile("cp.async.ca.shared.global [%0], [%1], 4;"  :: "r"(d), "l"(s))
#define CPCOMMIT()  asm volatile("cp.async.commit_group;")
#define CPWAIT1()   asm volatile("cp.async.wait_group 1;")
#define CPWAIT0()   asm volatile("cp.async.wait_group 0;")

// ---------------- per-column barrier (32 CTAs, contention-free release) ----------------
__device__ __forceinline__ void gsync_col(int col, int myIdx, unsigned gen) {
    __syncthreads();
    if (threadIdx.x == 0) {
        __threadfence();
        unsigned a = atomicAdd(&g_colcnt[col], 1u);
        if (a == 31u) {
            g_colcnt[col] = 0;
            __threadfence();
            #pragma unroll
            for (int i = 0; i < 32; i++) g_slot[col][i][0] = gen;
        } else {
            volatile unsigned* s = &g_slot[col][myIdx][0];
            while (*s < gen) { }
        }
        __threadfence();
    }
    __syncthreads();
}

// ---------------- init (runs every replay; resets barrier state) ----------------
__global__ void __launch_bounds__(128, 1) init_kernel() {
    int tid = threadIdx.x;
    if (tid < 4) g_colcnt[tid] = 0;
    g_slot[tid >> 5][tid & 31][0] = 0;
}

// =====================================================================
// BULK GEMM: 128x128 CTA tile, 256 threads, 8x8 micro-tile, KC=16,
// 3-stage cp.async pipeline. Epilogue writes gx TRANSPOSED [t4g][h][b].
// =====================================================================
#define BKC 16
#define BST (BKC * 132)   // floats per stage per operand

template <int NC>
__device__ __forceinline__ void bulk_seg(
    u64 acc[8][4], const float* __restrict__ A, int ldA,
    const float* __restrict__ W, int mBase, int nBase,
    float* Asm, float* Bsm)
{
    const int tid = threadIdx.x;
    const int tx = tid & 15, ty = tid >> 4;

    u32 asb[3], bsb[3];
    #pragma unroll
    for (int s = 0; s < 3; s++) {
        asb[s] = smem_u32(Asm + s * BST);
        bsb[s] = smem_u32(Bsm + s * BST);
    }

    auto issue = [&](int c) {
        int s = c % 3;
        #pragma unroll
        for (int e = 0; e < 2; e++) {
            int id = tid + 256 * e;
            int k = id >> 5, s32 = id & 31;
            const float* src = W + (size_t)(c * BKC + k) * G_DIM + nBase + s32 * 4;
            CP16(bsb[s] + (u32)(k * 132 + s32 * 4) * 4, src);
        }
        #pragma unroll
        for (int e = 0; e < 8; e++) {
            int id = tid + 256 * e;
            int k = id & 15, r = id >> 4;
            const float* src = A + (size_t)(mBase + r) * ldA + c * BKC + k;
            CP4(asb[s] + (u32)(k * 132 + r) * 4, src);
        }
        CPCOMMIT();
    };

    issue(0); issue(1);
    CPWAIT1(); __syncthreads();

    #pragma unroll 1
    for (int c = 0; c < NC; c++) {
        if (c + 2 < NC) issue(c + 2);
        const float* Ap = Asm + (c % 3) * BST;
        const float* Bp = Bsm + (c % 3) * BST;
        #pragma unroll
        for (int k = 0; k < BKC; k++) {
            float4 a0 = *(const float4*)(Ap + k * 132 + ty * 8);
            float4 a1 = *(const float4*)(Ap + k * 132 + ty * 8 + 4);
            float4 b0 = *(const float4*)(Bp + k * 132 + tx * 8);
            float4 b1 = *(const float4*)(Bp + k * 132 + tx * 8 + 4);
            u64 w[4] = { pack2(b0.x, b0.y), pack2(b0.z, b0.w),
                         pack2(b1.x, b1.y), pack2(b1.z, b1.w) };
            float am[8] = { a0.x, a0.y, a0.z, a0.w, a1.x, a1.y, a1.z, a1.w };
            #pragma unroll
            for (int m = 0; m < 8; m++) {
                u64 aa = pack2(am[m], am[m]);
                #pragma unroll
                for (int np = 0; np < 4; np++) fma2(acc[m][np], w[np], aa);
            }
        }
        if (c + 2 < NC) { CPWAIT1(); } else { CPWAIT0(); }
        __syncthreads();
    }
}

// Writes gx transposed: gx[(t*4+g)][h][b] = acc + bias
__device__ __forceinline__ void bulk_epilogue(
    u64 acc[8][4], const float* __restrict__ bias, int mBase, int nBase)
{
    const int tid = threadIdx.x;
    const int tx = tid & 15, ty = tid >> 4;
    const int t = mBase >> 8;
    const int b0 = (mBase & 255) + ty * 8;

    float4 bb0 = *(const float4*)(bias + nBase + tx * 8);
    float4 bb1 = *(const float4*)(bias + nBase + tx * 8 + 4);
    float bcol[8] = { bb0.x, bb0.y, bb0.z, bb0.w, bb1.x, bb1.y, bb1.z, bb1.w };

    float f[8][8];
    #pragma unroll
    for (int m = 0; m < 8; m++) {
        #pragma unroll
        for (int np = 0; np < 4; np++) {
            float lo, hi;
            unpack2(acc[m][np], lo, hi);
            f[m][2 * np]     = lo + bcol[2 * np];
            f[m][2 * np + 1] = hi + bcol[2 * np + 1];
        }
    }
    #pragma unroll
    for (int nn = 0; nn < 8; nn++) {
        int n = nBase + tx * 8 + nn;
        int g = n >> 9, h = n & 511;
        float* dst = g_gx + (((size_t)(t * 4 + g)) * H_DIM + h) * B_DIM + b0;
        float4 v0 = make_float4(f[0][nn], f[1][nn], f[2][nn], f[3][nn]);
        float4 v1 = make_float4(f[4][nn], f[5][nn], f[6][nn], f[7][nn]);
        *(float4*)dst = v0;
        *(float4*)(dst + 4) = v1;
    }
}

// layer0: gx = bias0 + x@Wih0 + b@Wbh0
__global__ void __launch_bounds__(256, 2) bulk0_kernel(
    const float* __restrict__ x, const float* __restrict__ br,
    const float* __restrict__ Wih, const float* __restrict__ Wbh,
    const float* __restrict__ bias)
{
    extern __shared__ __align__(16) float sm[];
    float* Asm = sm;
    float* Bsm = sm + 3 * BST;
    const int nBase = blockIdx.x * 128;
    const int mBase = blockIdx.y * 128;

    u64 acc[8][4] = {};
    bulk_seg<IN_DIM / BKC>(acc, x, IN_DIM, Wih, mBase, nBase, Asm, Bsm);
    bulk_seg<BR_DIM / BKC>(acc, br, BR_DIM, Wbh, mBase, nBase, Asm, Bsm);
    bulk_epilogue(acc, bias, mBase, nBase);
}

// layer1: gx = bias1 + hs0@Wih1, with hs0 stored transposed [t][h][b]
__global__ void __launch_bounds__(256, 2) bulk1_kernel(
    const float* __restrict__ Wih, const float* __restrict__ bias)
{
    extern __shared__ __align__(16) float sm[];
    float* Asm = sm;
    float* Bsm = sm + 3 * BST;
    const int tid = threadIdx.x;
    const int nBase = blockIdx.x * 128;
    const int mBase = blockIdx.y * 128;
    const int t = mBase >> 8;
    const int bo = mBase & 255;

    u32 asb[3], bsb[3];
    #pragma unroll
    for (int s = 0; s < 3; s++) {
        asb[s] = smem_u32(Asm + s * BST);
        bsb[s] = smem_u32(Bsm + s * BST);
    }

    auto issue = [&](int c) {
        int s = c % 3;
        #pragma unroll
        for (int e = 0; e < 2; e++) {
            int id = tid + 256 * e;
            int k = id >> 5, s32 = id & 31;
            const float* src = Wih + (size_t)(c * BKC + k) * G_DIM + nBase + s32 * 4;
            CP16(bsb[s] + (u32)(k * 132 + s32 * 4) * 4, src);
        }
        // A from g_hs0[t][k][b] : k-major rows, CP16, no transpose
        #pragma unroll
        for (int e = 0; e < 2; e++) {
            int id = tid + 256 * e;
            int k = id >> 5, seg = id & 31;
            const float* src = g_hs0 + ((size_t)t * H_DIM + c * BKC + k) * B_DIM + bo + seg * 4;
            CP16(asb[s] + (u32)(k * 132 + seg * 4) * 4, src);
        }
        CPCOMMIT();
    };

    u64 acc[8][4] = {};
    issue(0); issue(1);
    CPWAIT1(); __syncthreads();

    const int tx = tid & 15, ty = tid >> 4;
    #pragma unroll 1
    for (int c = 0; c < H_DIM / BKC; c++) {
        if (c + 2 < H_DIM / BKC) issue(c + 2);
        const float* Ap = Asm + (c % 3) * BST;
        const float* Bp = Bsm + (c % 3) * BST;
        #pragma unroll
        for (int k = 0; k < BKC; k++) {
            float4 a0 = *(const float4*)(Ap + k * 132 + ty * 8);
            float4 a1 = *(const float4*)(Ap + k * 132 + ty * 8 + 4);
            float4 b0 = *(const float4*)(Bp + k * 132 + tx * 8);
            float4 b1 = *(const float4*)(Bp + k * 132 + tx * 8 + 4);
            u64 w[4] = { pack2(b0.x, b0.y), pack2(b0.z, b0.w),
                         pack2(b1.x, b1.y), pack2(b1.z, b1.w) };
            float am[8] = { a0.x, a0.y, a0.z, a0.w, a1.x, a1.y, a1.z, a1.w };
            #pragma unroll
            for (int m = 0; m < 8; m++) {
                u64 aa = pack2(am[m], am[m]);
                #pragma unroll
                for (int np = 0; np < 4; np++) fma2(acc[m][np], w[np], aa);
            }
        }
        if (c + 2 < H_DIM / BKC) { CPWAIT1(); } else { CPWAIT0(); }
        __syncthreads();
    }
    bulk_epilogue(acc, bias, mBase, nBase);
}

// =====================================================================
// RECURRENT persistent kernel. Grid: 32 h-CTAs (16 h each, all 4 gates)
// x 4 b-CTAs (64 b). 256 THREADS (2 warps/SMSP for latency hiding).
// Thread (bq 0..31, hp 0..7) owns 2b x 2h x 4gates = 8 u64 accs (pair
// over h). W persistent in smem, repacked [k][hp][g][h2] so each thread
// reads all 4 gates with 2 LDS.128 (warp-broadcast). A streamed [k][b]
// via CP16, 8 chunks of 64k, 3-stage pipeline. gx LDGs issued at step
// top, consumed AFTER the GEMM. Per-b-column barrier.
// =====================================================================
#define RKC 64
#define RAST (RKC * 68)          // A stage floats (pad 68 keeps 16B align)
#define RW_FLOATS (H_DIM * 64)   // 32768 floats = 128 KB

__global__ void __launch_bounds__(256, 1) recur_kernel(
    int layer, const float* __restrict__ Whh, float* __restrict__ out)
{
    extern __shared__ __align__(16) float sm[];
    float* Wsm = sm;                    // [k512][hp8][g4][h2]
    float* Asm = sm + RW_FLOATS;        // 3 stages of [k64][68]

    const int tid = threadIdx.x;
    const int bq = tid & 31;            // b = bt0 + 2*bq + {0,1}
    const int hp = tid >> 5;            // h = ht0 + 2*hp + {0,1}
    const int ht0 = blockIdx.x * 16;    // gridDim.x = 32
    const int bt0 = blockIdx.y * 64;    // gridDim.y = 4
    const int col = blockIdx.y;         // barrier column
    const int myIdx = blockIdx.x;       // index within column

    u32 wsb = smem_u32(Wsm);
    u32 asb[3];
    #pragma unroll
    for (int s = 0; s < 3; s++) asb[s] = smem_u32(Asm + s * RAST);

    // ---- load W once, repacked: dst[k][hp][g][h2] <- Whh[k][g*512+ht0+2hp+{0,1}]
    // 512k * 8hp * 4g CP8 ops = 16384 / 256 threads = 64 each
    #pragma unroll 8
    for (int e = 0; e < 64; e++) {
        int id = tid + 256 * e;          // 0..16383
        int k = id >> 5;                 // 0..511
        int q = id & 31;                 // hp = q>>2, g = q&3
        int qhp = q >> 2, qg = q & 3;
        const float* src = Whh + (size_t)k * G_DIM + qg * H_DIM + ht0 + 2 * qhp;
        CP8(wsb + (u32)(k * 64 + qhp * 8 + qg * 2) * 4, src);
    }
    CPCOMMIT(); CPWAIT0(); __syncthreads();

    float cst[2][2] = {};                // [b][h]
    float hfin[2][2] = {};

    for (int t = 0; t < S_LEN; t++) {
        const float* Asrc = (layer == 0)
            ? g_hs0 + (size_t)(t - 1) * H_DIM * B_DIM
            : g_h1t[t & 1];

        auto issueA = [&](int c) {
            int s = c % 3;
            // 64k x 64b floats = 1024 CP16 / 256 threads = 4 each
            #pragma unroll
            for (int e = 0; e < 4; e++) {
                int id = tid + 256 * e;
                int k = id >> 4, seg = id & 15;
                const float* src = Asrc + (size_t)(c * RKC + k) * B_DIM + bt0 + seg * 4;
                CP16(asb[s] + (u32)(k * 68 + seg * 4) * 4, src);
            }
            CPCOMMIT();
        };

        if (t > 0) { issueA(0); issueA(1); }

        // ---- gx LDGs issued now, consumed only after the GEMM ----
        float2 gxv[4][2];   // [g][hh]
        const float* gxb = g_gx + (size_t)t * 4 * H_DIM * B_DIM;
        #pragma unroll
        for (int g = 0; g < 4; g++) {
            #pragma unroll
            for (int hh = 0; hh < 2; hh++) {
                gxv[g][hh] = *(const float2*)(
                    gxb + ((size_t)g * H_DIM + ht0 + 2 * hp + hh) * B_DIM + bt0 + 2 * bq);
            }
        }

        u64 acc[2][4] = {};  // [b][gate], pair over (h0,h1)

        if (t > 0) {
            CPWAIT1(); __syncthreads();

            #pragma unroll 1
            for (int c = 0; c < 8; c++) {
                if (c < 6) issueA(c + 2);
                const float* Ap = Asm + (c % 3) * RAST;
                const float* Wp = Wsm + c * (RKC * 64);
                #pragma unroll 8
                for (int k = 0; k < RKC; k++) {
                    float2 af = *(const float2*)(Ap + k * 68 + 2 * bq);
                    ulonglong2 wA = *(const ulonglong2*)(Wp + k * 64 + hp * 8);      // g0,g1
                    ulonglong2 wB = *(const ulonglong2*)(Wp + k * 64 + hp * 8 + 4);  // g2,g3
                    u64 aa0 = pack2(af.x, af.x);
                    u64 aa1 = pack2(af.y, af.y);
                    fma2(acc[0][0], wA.x, aa0);
                    fma2(acc[0][1], wA.y, aa0);
                    fma2(acc[0][2], wB.x, aa0);
                    fma2(acc[0][3], wB.y, aa0);
                    fma2(acc[1][0], wA.x, aa1);
                    fma2(acc[1][1], wA.y, aa1);
                    fma2(acc[1][2], wB.x, aa1);
                    fma2(acc[1][3], wB.y, aa1);
                }
                if (c < 6) { CPWAIT1(); } else { CPWAIT0(); }
                __syncthreads();
            }
        }

        // ---- add input-side preacts (gx): acc[b][g] += (gx_h0, gx_h1) ----
        #pragma unroll
        for (int g = 0; g < 4; g++) {
            #pragma unroll
            for (int b = 0; b < 2; b++) {
                float lo = (b == 0) ? gxv[g][0].x : gxv[g][0].y;
                float hi = (b == 0) ? gxv[g][1].x : gxv[g][1].y;
                add2(acc[b][g], pack2(lo, hi));
            }
        }

        // ---- gates (cells: 2b x 2h) ----
        #pragma unroll
        for (int b = 0; b < 2; b++) {
            float i0, i1, f0, f1, q0, q1, o0, o1;
            unpack2(acc[b][0], i0, i1);
            unpack2(acc[b][1], f0, f1);
            unpack2(acc[b][2], q0, q1);
            unpack2(acc[b][3], o0, o1);
            float c0 = fast_sigmoid(f0) * cst[b][0] + fast_sigmoid(i0) * fast_tanh(q0);
            float c1 = fast_sigmoid(f1) * cst[b][1] + fast_sigmoid(i1) * fast_tanh(q1);
            cst[b][0] = c0; cst[b][1] = c1;
            hfin[b][0] = fast_sigmoid(o0) * fast_tanh(c0);
            hfin[b][1] = fast_sigmoid(o1) * fast_tanh(c1);
        }

        // ---- stores ----
        if (layer == 0) {
            #pragma unroll
            for (int hh = 0; hh < 2; hh++) {
                float2 v = make_float2(hfin[0][hh], hfin[1][hh]);
                *(float2*)(g_hs0 + ((size_t)t * H_DIM + ht0 + 2 * hp + hh) * B_DIM
                           + bt0 + 2 * bq) = v;
            }
        } else {
            float* hb = g_h1t[(t + 1) & 1];
            #pragma unroll
            for (int hh = 0; hh < 2; hh++) {
                float2 v = make_float2(hfin[0][hh], hfin[1][hh]);
                *(float2*)(hb + ((size_t)(ht0 + 2 * hp + hh)) * B_DIM + bt0 + 2 * bq) = v;
            }
            #pragma unroll
            for (int b = 0; b < 2; b++) {
                *(float2*)(out + ((size_t)t * B_DIM + bt0 + 2 * bq + b) * H_DIM
                           + ht0 + 2 * hp) = make_float2(hfin[b][0], hfin[b][1]);
            }
        }

        gsync_col(col, myIdx, (layer == 0 ? 0u : (unsigned)S_LEN) + (unsigned)t + 1u);
    }

    // ---- finals: h_n, c_n ----
    const size_t base = (size_t)S_LEN * B_DIM * H_DIM;
    const size_t BH = (size_t)B_DIM * H_DIM;
    #pragma unroll
    for (int b = 0; b < 2; b++) {
        size_t row = (size_t)(bt0 + 2 * bq + b) * H_DIM + ht0 + 2 * hp;
        *(float2*)(out + base + (size_t)layer * BH + row) =
            make_float2(hfin[b][0], hfin[b][1]);
        *(float2*)(out + base + (2 + (size_t)layer) * BH + row) =
            make_float2(cst[b][0], cst[b][1]);
    }
}

// =====================================================================
extern "C" void kernel_launch(void* const* d_in, const int* in_sizes, int n_in,
                              void* d_out, int out_size)
{
    const float* x    = (const float*)d_in[0];  // [S, B, IN]
    const float* br   = (const float*)d_in[1];  // [S, B, BR]
    const float* Wih0 = (const float*)d_in[2];  // [IN, 4H]
    const float* Wbh0 = (const float*)d_in[3];  // [BR, 4H]
    const float* Whh0 = (const float*)d_in[4];  // [H, 4H]
    const float* b0   = (const float*)d_in[5];  // [4H]
    const float* Wih1 = (const float*)d_in[6];  // [H, 4H]
    const float* Whh1 = (const float*)d_in[7];  // [H, 4H]
    const float* b1   = (const float*)d_in[8];  // [4H]
    float* out = (float*)d_out;

    const int bulk_smem  = 3 * BST * 2 * sizeof(float);            // 50688
    const int recur_smem = (RW_FLOATS + 3 * RAST) * sizeof(float); // 183296

    cudaFuncSetAttribute(bulk0_kernel, cudaFuncAttributeMaxDynamicSharedMemorySize, bulk_smem);
    cudaFuncSetAttribute(bulk1_kernel, cudaFuncAttributeMaxDynamicSharedMemorySize, bulk_smem);
    cudaFuncSetAttribute(recur_kernel, cudaFuncAttributeMaxDynamicSharedMemorySize, recur_smem);

    init_kernel<<<1, 128>>>();

    dim3 bulk_grid(G_DIM / 128, M_DIM / 128);  // (16, 1024)
    dim3 rec_grid(H_DIM / 16, B_DIM / 64);     // (32, 4) = 128 CTAs

    bulk0_kernel<<<bulk_grid, 256, bulk_smem>>>(x, br, Wih0, Wbh0, b0);
    recur_kernel<<<rec_grid, 256, recur_smem>>>(0, Whh0, out);
    bulk1_kernel<<<bulk_grid, 256, bulk_smem>>>(Wih1, b1);
    recur_kernel<<<rec_grid, 256, recur_smem>>>(1, Whh1, out);
}

// round 14
// speedup vs baseline: 1.0081x; 1.0081x over previous
#include <cuda_runtime.h>
#include <math.h>

typedef unsigned long long u64;
typedef unsigned int u32;

#define S_LEN 512
#define B_DIM 256
#define IN_DIM 256
#define BR_DIM 128
#define H_DIM 512
#define G_DIM 2048                 // 4*H
#define M_DIM (S_LEN * B_DIM)      // 131072

// ---------------- device scratch (no allocations allowed) ----------------
// gx layout: [(t*4+g)][h:512][b:256]  (transposed, 1 GiB)
__device__ float g_gx[(size_t)M_DIM * G_DIM];
// hs0 layout: [t][h:512][b:256]  (transposed, 256 MiB) -- doubles as layer-0 h history
__device__ float g_hs0[(size_t)S_LEN * H_DIM * B_DIM];
__device__ float g_h1t[2][H_DIM * B_DIM];               // layer-1 h double buffer, [h][b]

// per-b-column barrier state: 4 columns x 32 CTAs, slots padded to 128B lines
__device__ unsigned g_colcnt[4];
__device__ volatile unsigned g_slot[4][32][32];

// ---------------- packed f32x2 + activation helpers ----------------
__device__ __forceinline__ u64 pack2(float lo, float hi) {
    u64 r; asm("mov.b64 %0, {%1, %2};" : "=l"(r) : "f"(lo), "f"(hi)); return r;
}
__device__ __forceinline__ void unpack2(u64 v, float& lo, float& hi) {
    asm("mov.b64 {%0, %1}, %2;" : "=f"(lo), "=f"(hi) : "l"(v));
}
__device__ __forceinline__ void fma2(u64& d, u64 a, u64 b) {
    asm("fma.rn.f32x2 %0, %1, %2, %0;" : "+l"(d) : "l"(a), "l"(b));
}
__device__ __forceinline__ void add2(u64& d, u64 a) {
    asm("add.rn.f32x2 %0, %0, %1;" : "+l"(d) : "l"(a));
}
__device__ __forceinline__ float fast_sigmoid(float x) { return 1.0f / (1.0f + __expf(-x)); }
__device__ __forceinline__ float fast_tanh(float x) { return 1.0f - 2.0f / (__expf(2.0f * x) + 1.0f); }

// ---------------- cp.async ----------------
__device__ __forceinline__ u32 smem_u32(const void* p) {
    return (u32)__cvta_generic_to_shared(p);
}
#define CP16(d, s)  asm volatile("cp.async.cg.shared.global [%0], [%1], 16;" :: "r"(d), "l"(s))
#define CP4(d, s)   asm volatile("cp.async.ca.shared.global [%0], [%1], 4;"  :: "r"(d), "l"(s))
#define CPCOMMIT()  asm volatile("cp.async.commit_group;")
#define CPWAIT1()   asm volatile("cp.async.wait_group 1;")
#define CPWAIT0()   asm volatile("cp.async.wait_group 0;")

// ---------------- per-column barrier (32 CTAs, contention-free release) ----------------
__device__ __forceinline__ void gsync_col(int col, int myIdx, unsigned gen) {
    __syncthreads();
    if (threadIdx.x == 0) {
        __threadfence();
        unsigned a = atomicAdd(&g_colcnt[col], 1u);
        if (a == 31u) {
            g_colcnt[col] = 0;
            __threadfence();
            #pragma unroll
            for (int i = 0; i < 32; i++) g_slot[col][i][0] = gen;
        } else {
            volatile unsigned* s = &g_slot[col][myIdx][0];
            while (*s < gen) { }
        }
        __threadfence();
    }
    __syncthreads();
}

// ---------------- init (runs every replay; resets barrier state) ----------------
__global__ void __launch_bounds__(128, 1) init_kernel() {
    int tid = threadIdx.x;
    if (tid < 4) g_colcnt[tid] = 0;
    g_slot[tid >> 5][tid & 31][0] = 0;
}

// =====================================================================
// BULK GEMM: 128x128 CTA tile, 256 threads, 8x8 micro-tile, KC=16,
// 3-stage cp.async pipeline. Epilogue writes gx TRANSPOSED [t4g][h][b].
// =====================================================================
#define BKC 16
#define BST (BKC * 132)   // floats per stage per operand

template <int NC>
__device__ __forceinline__ void bulk_seg(
    u64 acc[8][4], const float* __restrict__ A, int ldA,
    const float* __restrict__ W, int mBase, int nBase,
    float* Asm, float* Bsm)
{
    const int tid = threadIdx.x;
    const int tx = tid & 15, ty = tid >> 4;

    u32 asb[3], bsb[3];
    #pragma unroll
    for (int s = 0; s < 3; s++) {
        asb[s] = smem_u32(Asm + s * BST);
        bsb[s] = smem_u32(Bsm + s * BST);
    }

    auto issue = [&](int c) {
        int s = c % 3;
        #pragma unroll
        for (int e = 0; e < 2; e++) {
            int id = tid + 256 * e;
            int k = id >> 5, s32 = id & 31;
            const float* src = W + (size_t)(c * BKC + k) * G_DIM + nBase + s32 * 4;
            CP16(bsb[s] + (u32)(k * 132 + s32 * 4) * 4, src);
        }
        #pragma unroll
        for (int e = 0; e < 8; e++) {
            int id = tid + 256 * e;
            int k = id & 15, r = id >> 4;
            const float* src = A + (size_t)(mBase + r) * ldA + c * BKC + k;
            CP4(asb[s] + (u32)(k * 132 + r) * 4, src);
        }
        CPCOMMIT();
    };

    issue(0); issue(1);
    CPWAIT1(); __syncthreads();

    #pragma unroll 1
    for (int c = 0; c < NC; c++) {
        if (c + 2 < NC) issue(c + 2);
        const float* Ap = Asm + (c % 3) * BST;
        const float* Bp = Bsm + (c % 3) * BST;
        #pragma unroll
        for (int k = 0; k < BKC; k++) {
            float4 a0 = *(const float4*)(Ap + k * 132 + ty * 8);
            float4 a1 = *(const float4*)(Ap + k * 132 + ty * 8 + 4);
            float4 b0 = *(const float4*)(Bp + k * 132 + tx * 8);
            float4 b1 = *(const float4*)(Bp + k * 132 + tx * 8 + 4);
            u64 w[4] = { pack2(b0.x, b0.y), pack2(b0.z, b0.w),
                         pack2(b1.x, b1.y), pack2(b1.z, b1.w) };
            float am[8] = { a0.x, a0.y, a0.z, a0.w, a1.x, a1.y, a1.z, a1.w };
            #pragma unroll
            for (int m = 0; m < 8; m++) {
                u64 aa = pack2(am[m], am[m]);
                #pragma unroll
                for (int np = 0; np < 4; np++) fma2(acc[m][np], w[np], aa);
            }
        }
        if (c + 2 < NC) { CPWAIT1(); } else { CPWAIT0(); }
        __syncthreads();
    }
}

// Writes gx transposed: gx[(t*4+g)][h][b] = acc + bias
__device__ __forceinline__ void bulk_epilogue(
    u64 acc[8][4], const float* __restrict__ bias, int mBase, int nBase)
{
    const int tid = threadIdx.x;
    const int tx = tid & 15, ty = tid >> 4;
    const int t = mBase >> 8;
    const int b0 = (mBase & 255) + ty * 8;

    float4 bb0 = *(const float4*)(bias + nBase + tx * 8);
    float4 bb1 = *(const float4*)(bias + nBase + tx * 8 + 4);
    float bcol[8] = { bb0.x, bb0.y, bb0.z, bb0.w, bb1.x, bb1.y, bb1.z, bb1.w };

    float f[8][8];
    #pragma unroll
    for (int m = 0; m < 8; m++) {
        #pragma unroll
        for (int np = 0; np < 4; np++) {
            float lo, hi;
            unpack2(acc[m][np], lo, hi);
            f[m][2 * np]     = lo + bcol[2 * np];
            f[m][2 * np + 1] = hi + bcol[2 * np + 1];
        }
    }
    #pragma unroll
    for (int nn = 0; nn < 8; nn++) {
        int n = nBase + tx * 8 + nn;
        int g = n >> 9, h = n & 511;
        float* dst = g_gx + (((size_t)(t * 4 + g)) * H_DIM + h) * B_DIM + b0;
        float4 v0 = make_float4(f[0][nn], f[1][nn], f[2][nn], f[3][nn]);
        float4 v1 = make_float4(f[4][nn], f[5][nn], f[6][nn], f[7][nn]);
        *(float4*)dst = v0;
        *(float4*)(dst + 4) = v1;
    }
}

// layer0: gx = bias0 + x@Wih0 + b@Wbh0
__global__ void __launch_bounds__(256, 2) bulk0_kernel(
    const float* __restrict__ x, const float* __restrict__ br,
    const float* __restrict__ Wih, const float* __restrict__ Wbh,
    const float* __restrict__ bias)
{
    extern __shared__ __align__(16) float sm[];
    float* Asm = sm;
    float* Bsm = sm + 3 * BST;
    const int nBase = blockIdx.x * 128;
    const int mBase = blockIdx.y * 128;

    u64 acc[8][4] = {};
    bulk_seg<IN_DIM / BKC>(acc, x, IN_DIM, Wih, mBase, nBase, Asm, Bsm);
    bulk_seg<BR_DIM / BKC>(acc, br, BR_DIM, Wbh, mBase, nBase, Asm, Bsm);
    bulk_epilogue(acc, bias, mBase, nBase);
}

// layer1: gx = bias1 + hs0@Wih1, with hs0 stored transposed [t][h][b]
__global__ void __launch_bounds__(256, 2) bulk1_kernel(
    const float* __restrict__ Wih, const float* __restrict__ bias)
{
    extern __shared__ __align__(16) float sm[];
    float* Asm = sm;
    float* Bsm = sm + 3 * BST;
    const int tid = threadIdx.x;
    const int nBase = blockIdx.x * 128;
    const int mBase = blockIdx.y * 128;
    const int t = mBase >> 8;
    const int bo = mBase & 255;

    u32 asb[3], bsb[3];
    #pragma unroll
    for (int s = 0; s < 3; s++) {
        asb[s] = smem_u32(Asm + s * BST);
        bsb[s] = smem_u32(Bsm + s * BST);
    }

    auto issue = [&](int c) {
        int s = c % 3;
        #pragma unroll
        for (int e = 0; e < 2; e++) {
            int id = tid + 256 * e;
            int k = id >> 5, s32 = id & 31;
            const float* src = Wih + (size_t)(c * BKC + k) * G_DIM + nBase + s32 * 4;
            CP16(bsb[s] + (u32)(k * 132 + s32 * 4) * 4, src);
        }
        // A from g_hs0[t][k][b] : k-major rows, CP16, no transpose
        #pragma unroll
        for (int e = 0; e < 2; e++) {
            int id = tid + 256 * e;
            int k = id >> 5, seg = id & 31;
            const float* src = g_hs0 + ((size_t)t * H_DIM + c * BKC + k) * B_DIM + bo + seg * 4;
            CP16(asb[s] + (u32)(k * 132 + seg * 4) * 4, src);
        }
        CPCOMMIT();
    };

    u64 acc[8][4] = {};
    issue(0); issue(1);
    CPWAIT1(); __syncthreads();

    const int tx = tid & 15, ty = tid >> 4;
    #pragma unroll 1
    for (int c = 0; c < H_DIM / BKC; c++) {
        if (c + 2 < H_DIM / BKC) issue(c + 2);
        const float* Ap = Asm + (c % 3) * BST;
        const float* Bp = Bsm + (c % 3) * BST;
        #pragma unroll
        for (int k = 0; k < BKC; k++) {
            float4 a0 = *(const float4*)(Ap + k * 132 + ty * 8);
            float4 a1 = *(const float4*)(Ap + k * 132 + ty * 8 + 4);
            float4 b0 = *(const float4*)(Bp + k * 132 + tx * 8);
            float4 b1 = *(const float4*)(Bp + k * 132 + tx * 8 + 4);
            u64 w[4] = { pack2(b0.x, b0.y), pack2(b0.z, b0.w),
                         pack2(b1.x, b1.y), pack2(b1.z, b1.w) };
            float am[8] = { a0.x, a0.y, a0.z, a0.w, a1.x, a1.y, a1.z, a1.w };
            #pragma unroll
            for (int m = 0; m < 8; m++) {
                u64 aa = pack2(am[m], am[m]);
                #pragma unroll
                for (int np = 0; np < 4; np++) fma2(acc[m][np], w[np], aa);
            }
        }
        if (c + 2 < H_DIM / BKC) { CPWAIT1(); } else { CPWAIT0(); }
        __syncthreads();
    }
    bulk_epilogue(acc, bias, mBase, nBase);
}

// =====================================================================
// RECURRENT persistent kernel. Grid: 32 h-CTAs (16 h, all 4 gates) x
// 4 b-CTAs (64 b). 128 threads. Warp w owns b slice [bt0+16w,+16);
// lane (bl=lane&7, hl=lane>>3) owns 2b x 4h x 4g = 32 cells.
// Per k: 1 LDS.64 (a, 8 distinct addrs) + 4 LDS.128 (w, 4 distinct,
// conflict-free via [k][g][hl][4] layout) + 16 FFMA2  -> 20 wf/SM/k vs
// 32 FMA cyc/k: FMA-bound with crossbar slack.
// W persistent in smem (128 KB). A streamed [k][b] via CP16, 4 chunks
// of 128k, 2-stage pipeline. gx LDGs at step top, consumed after GEMM.
// =====================================================================
#define RKC 128
#define RAST (RKC * 64)          // A stage floats (32 KB)
#define RW_FLOATS (H_DIM * 64)   // 32768 floats = 128 KB, [k][g][hl][4]

__global__ void __launch_bounds__(128, 1) recur_kernel(
    int layer, const float* __restrict__ Whh, float* __restrict__ out)
{
    extern __shared__ __align__(16) float sm[];
    float* Wsm = sm;                    // [k512][g4][hl4][4]
    float* Asm = sm + RW_FLOATS;        // 2 stages of [k128][64]

    const int tid = threadIdx.x;
    const int w = tid >> 5;
    const int lane = tid & 31;
    const int bl = lane & 7;
    const int hl = lane >> 3;           // 0..3
    const int ht0 = blockIdx.x * 16;    // gridDim.x = 32
    const int bt0 = blockIdx.y * 64;    // gridDim.y = 4
    const int col = blockIdx.y;
    const int myIdx = blockIdx.x;

    const int bofs = w * 16 + 2 * bl;   // local b offset (2 consecutive b)
    const int b0 = bt0 + bofs;
    const int h0 = ht0 + 4 * hl;        // 4 consecutive h

    u32 wsb = smem_u32(Wsm);
    u32 asb[2] = { smem_u32(Asm), smem_u32(Asm + RAST) };

    // ---- load W once, repacked: dst[k][g][hl][0..3] <- Whh[k][g*512+ht0+4*hl+{0..3}]
    // 512k * 4g * 4hl CP16 = 8192 / 128 threads = 64 each
    #pragma unroll 8
    for (int e = 0; e < 64; e++) {
        int id = tid + 128 * e;          // 0..8191
        int k = id >> 4;
        int q = id & 15;                 // g = q>>2, hq = q&3
        int qg = q >> 2, qh = q & 3;
        const float* src = Whh + (size_t)k * G_DIM + qg * H_DIM + ht0 + qh * 4;
        CP16(wsb + (u32)(k * 64 + qg * 16 + qh * 4) * 4, src);
    }
    CPCOMMIT(); CPWAIT0(); __syncthreads();

    float cst[2][4] = {};                // [b][h]
    float hfin[2][4] = {};

    for (int t = 0; t < S_LEN; t++) {
        const float* Asrc = (layer == 0)
            ? g_hs0 + (size_t)(t - 1) * H_DIM * B_DIM
            : g_h1t[t & 1];

        auto issueA = [&](int c) {
            int s = c & 1;
            // 128k x 64b floats = 32KB = 2048 CP16 / 128 threads = 16 each
            #pragma unroll
            for (int e = 0; e < 16; e++) {
                int id = tid + 128 * e;
                int k = id >> 4, seg = id & 15;
                const float* src = Asrc + (size_t)(c * RKC + k) * B_DIM + bt0 + seg * 4;
                CP16(asb[s] + (u32)(k * 64 + seg * 4) * 4, src);
            }
            CPCOMMIT();
        };

        if (t > 0) issueA(0);

        // ---- gx LDGs issued now, consumed only after the GEMM ----
        // gxp[g][hh] = float2 over (b0, b0+1) for h = h0 + hh
        float2 gxp[4][4];
        const float* gxb = g_gx + (size_t)t * 4 * H_DIM * B_DIM;
        #pragma unroll
        for (int g = 0; g < 4; g++) {
            #pragma unroll
            for (int hh = 0; hh < 4; hh++) {
                gxp[g][hh] = *(const float2*)(
                    gxb + ((size_t)g * H_DIM + h0 + hh) * B_DIM + b0);
            }
        }

        u64 acc[2][4][2] = {};  // [b][g][hpair], pair over (h+0,h+1)/(h+2,h+3)

        if (t > 0) {
            #pragma unroll 1
            for (int c = 0; c < 4; c++) {
                if (c + 1 < 4) issueA(c + 1);
                if (c + 1 < 4) { CPWAIT1(); } else { CPWAIT0(); }
                __syncthreads();
                const float* Ap = Asm + (c & 1) * RAST;
                const float* Wp = Wsm + c * (RKC * 64);
                #pragma unroll 8
                for (int k = 0; k < RKC; k++) {
                    float2 af = *(const float2*)(Ap + k * 64 + bofs);
                    u64 aa0 = pack2(af.x, af.x);
                    u64 aa1 = pack2(af.y, af.y);
                    #pragma unroll
                    for (int g = 0; g < 4; g++) {
                        ulonglong2 wv = *(const ulonglong2*)(Wp + k * 64 + g * 16 + hl * 4);
                        fma2(acc[0][g][0], wv.x, aa0);
                        fma2(acc[0][g][1], wv.y, aa0);
                        fma2(acc[1][g][0], wv.x, aa1);
                        fma2(acc[1][g][1], wv.y, aa1);
                    }
                }
                __syncthreads();
            }
        }

        // ---- add input-side preacts (gx) ----
        #pragma unroll
        for (int g = 0; g < 4; g++) {
            #pragma unroll
            for (int b = 0; b < 2; b++) {
                float v0 = (b == 0) ? gxp[g][0].x : gxp[g][0].y;
                float v1 = (b == 0) ? gxp[g][1].x : gxp[g][1].y;
                float v2 = (b == 0) ? gxp[g][2].x : gxp[g][2].y;
                float v3 = (b == 0) ? gxp[g][3].x : gxp[g][3].y;
                add2(acc[b][g][0], pack2(v0, v1));
                add2(acc[b][g][1], pack2(v2, v3));
            }
        }

        // ---- gates (cells: 2b x 4h) ----
        #pragma unroll
        for (int b = 0; b < 2; b++) {
            #pragma unroll
            for (int p = 0; p < 2; p++) {
                float i0, i1, f0, f1, q0, q1, o0, o1;
                unpack2(acc[b][0][p], i0, i1);
                unpack2(acc[b][1][p], f0, f1);
                unpack2(acc[b][2][p], q0, q1);
                unpack2(acc[b][3][p], o0, o1);
                float c0 = fast_sigmoid(f0) * cst[b][2 * p + 0] + fast_sigmoid(i0) * fast_tanh(q0);
                float c1 = fast_sigmoid(f1) * cst[b][2 * p + 1] + fast_sigmoid(i1) * fast_tanh(q1);
                cst[b][2 * p + 0] = c0; cst[b][2 * p + 1] = c1;
                hfin[b][2 * p + 0] = fast_sigmoid(o0) * fast_tanh(c0);
                hfin[b][2 * p + 1] = fast_sigmoid(o1) * fast_tanh(c1);
            }
        }

        // ---- stores ----
        if (layer == 0) {
            #pragma unroll
            for (int hh = 0; hh < 4; hh++) {
                *(float2*)(g_hs0 + ((size_t)t * H_DIM + h0 + hh) * B_DIM + b0) =
                    make_float2(hfin[0][hh], hfin[1][hh]);
            }
        } else {
            float* hb = g_h1t[(t + 1) & 1];
            #pragma unroll
            for (int hh = 0; hh < 4; hh++) {
                *(float2*)(hb + ((size_t)(h0 + hh)) * B_DIM + b0) =
                    make_float2(hfin[0][hh], hfin[1][hh]);
            }
            #pragma unroll
            for (int b = 0; b < 2; b++) {
                *(float4*)(out + ((size_t)t * B_DIM + b0 + b) * H_DIM + h0) =
                    make_float4(hfin[b][0], hfin[b][1], hfin[b][2], hfin[b][3]);
            }
        }

        gsync_col(col, myIdx, (layer == 0 ? 0u : (unsigned)S_LEN) + (unsigned)t + 1u);
    }

    // ---- finals: h_n, c_n ----
    const size_t base = (size_t)S_LEN * B_DIM * H_DIM;
    const size_t BH = (size_t)B_DIM * H_DIM;
    #pragma unroll
    for (int b = 0; b < 2; b++) {
        size_t row = (size_t)(b0 + b) * H_DIM + h0;
        *(float4*)(out + base + (size_t)layer * BH + row) =
            make_float4(hfin[b][0], hfin[b][1], hfin[b][2], hfin[b][3]);
        *(float4*)(out + base + (2 + (size_t)layer) * BH + row) =
            make_float4(cst[b][0], cst[b][1], cst[b][2], cst[b][3]);
    }
}

// =====================================================================
extern "C" void kernel_launch(void* const* d_in, const int* in_sizes, int n_in,
                              void* d_out, int out_size)
{
    const float* x    = (const float*)d_in[0];  // [S, B, IN]
    const float* br   = (const float*)d_in[1];  // [S, B, BR]
    const float* Wih0 = (const float*)d_in[2];  // [IN, 4H]
    const float* Wbh0 = (const float*)d_in[3];  // [BR, 4H]
    const float* Whh0 = (const float*)d_in[4];  // [H, 4H]
    const float* b0   = (const float*)d_in[5];  // [4H]
    const float* Wih1 = (const float*)d_in[6];  // [H, 4H]
    const float* Whh1 = (const float*)d_in[7];  // [H, 4H]
    const float* b1   = (const float*)d_in[8];  // [4H]
    float* out = (float*)d_out;

    const int bulk_smem  = 3 * BST * 2 * sizeof(float);            // 50688
    const int recur_smem = (RW_FLOATS + 2 * RAST) * sizeof(float); // 196608

    cudaFuncSetAttribute(bulk0_kernel, cudaFuncAttributeMaxDynamicSharedMemorySize, bulk_smem);
    cudaFuncSetAttribute(bulk1_kernel, cudaFuncAttributeMaxDynamicSharedMemorySize, bulk_smem);
    cudaFuncSetAttribute(recur_kernel, cudaFuncAttributeMaxDynamicSharedMemorySize, recur_smem);

    init_kernel<<<1, 128>>>();

    dim3 bulk_grid(G_DIM / 128, M_DIM / 128);  // (16, 1024)
    dim3 rec_grid(H_DIM / 16, B_DIM / 64);     // (32, 4) = 128 CTAs

    bulk0_kernel<<<bulk_grid, 256, bulk_smem>>>(x, br, Wih0, Wbh0, b0);
    recur_kernel<<<rec_grid, 128, recur_smem>>>(0, Whh0, out);
    bulk1_kernel<<<bulk_grid, 256, bulk_smem>>>(Wih1, b1);
    recur_kernel<<<rec_grid, 128, recur_smem>>>(1, Whh1, out);
}

// round 16
// speedup vs baseline: 1.0621x; 1.0536x over previous
#include <cuda_runtime.h>
#include <math.h>

typedef unsigned long long u64;
typedef unsigned int u32;

#define S_LEN 512
#define B_DIM 256
#define IN_DIM 256
#define BR_DIM 128
#define H_DIM 512
#define G_DIM 2048                 // 4*H
#define M_DIM (S_LEN * B_DIM)      // 131072

// ---------------- device scratch (no allocations allowed) ----------------
// gx layout: [(t*4+g)][h:512][b:256]  (transposed, 1 GiB)
__device__ float g_gx[(size_t)M_DIM * G_DIM];
// hs0 layout: [t][h:512][b:256]  (transposed, 256 MiB) -- doubles as layer-0 h history
__device__ float g_hs0[(size_t)S_LEN * H_DIM * B_DIM];
__device__ float g_h1t[2][H_DIM * B_DIM];               // layer-1 h double buffer, [h][b]

// per-b-column barrier state: 4 columns x 32 CTAs, slots padded to 128B lines
__device__ unsigned g_colcnt[4];
__device__ volatile unsigned g_slot[4][32][32];

// ---------------- packed f32x2 + activation helpers ----------------
__device__ __forceinline__ u64 pack2(float lo, float hi) {
    u64 r; asm("mov.b64 %0, {%1, %2};" : "=l"(r) : "f"(lo), "f"(hi)); return r;
}
__device__ __forceinline__ void unpack2(u64 v, float& lo, float& hi) {
    asm("mov.b64 {%0, %1}, %2;" : "=f"(lo), "=f"(hi) : "l"(v));
}
__device__ __forceinline__ void fma2(u64& d, u64 a, u64 b) {
    asm("fma.rn.f32x2 %0, %1, %2, %0;" : "+l"(d) : "l"(a), "l"(b));
}
__device__ __forceinline__ void add2(u64& d, u64 a) {
    asm("add.rn.f32x2 %0, %0, %1;" : "+l"(d) : "l"(a));
}
__device__ __forceinline__ float fast_sigmoid(float x) { return 1.0f / (1.0f + __expf(-x)); }
__device__ __forceinline__ float fast_tanh(float x) { return 1.0f - 2.0f / (__expf(2.0f * x) + 1.0f); }

// ---------------- cp.async ----------------
__device__ __forceinline__ u32 smem_u32(const void* p) {
    return (u32)__cvta_generic_to_shared(p);
}
#define CP16(d, s)  asm volatile("cp.async.cg.shared.global [%0], [%1], 16;" :: "r"(d), "l"(s))
#define CP4(d, s)   asm volatile("cp.async.ca.shared.global [%0], [%1], 4;"  :: "r"(d), "l"(s))
#define CPCOMMIT()  asm volatile("cp.async.commit_group;")
#define CPWAIT1()   asm volatile("cp.async.wait_group 1;")
#define CPWAIT0()   asm volatile("cp.async.wait_group 0;")

// ---------------- per-column barrier (32 CTAs, contention-free release) ----------------
__device__ __forceinline__ void gsync_col(int col, int myIdx, unsigned gen) {
    __syncthreads();
    if (threadIdx.x == 0) {
        __threadfence();
        unsigned a = atomicAdd(&g_colcnt[col], 1u);
        if (a == 31u) {
            g_colcnt[col] = 0;
            __threadfence();
            #pragma unroll
            for (int i = 0; i < 32; i++) g_slot[col][i][0] = gen;
        } else {
            volatile unsigned* s = &g_slot[col][myIdx][0];
            while (*s < gen) { }
        }
        __threadfence();
    }
    __syncthreads();
}

// ---------------- init (runs every replay; resets barrier state) ----------------
__global__ void __launch_bounds__(128, 1) init_kernel() {
    int tid = threadIdx.x;
    if (tid < 4) g_colcnt[tid] = 0;
    g_slot[tid >> 5][tid & 31][0] = 0;
}

// =====================================================================
// BULK GEMM: 128x128 CTA tile, 256 threads, 8x8 micro-tile, KC=16,
// 3-stage cp.async pipeline. Epilogue writes gx TRANSPOSED [t4g][h][b].
// =====================================================================
#define BKC 16
#define BST (BKC * 132)   // floats per stage per operand

template <int NC>
__device__ __forceinline__ void bulk_seg(
    u64 acc[8][4], const float* __restrict__ A, int ldA,
    const float* __restrict__ W, int mBase, int nBase,
    float* Asm, float* Bsm)
{
    const int tid = threadIdx.x;
    const int tx = tid & 15, ty = tid >> 4;

    u32 asb[3], bsb[3];
    #pragma unroll
    for (int s = 0; s < 3; s++) {
        asb[s] = smem_u32(Asm + s * BST);
        bsb[s] = smem_u32(Bsm + s * BST);
    }

    auto issue = [&](int c) {
        int s = c % 3;
        #pragma unroll
        for (int e = 0; e < 2; e++) {
            int id = tid + 256 * e;
            int k = id >> 5, s32 = id & 31;
            const float* src = W + (size_t)(c * BKC + k) * G_DIM + nBase + s32 * 4;
            CP16(bsb[s] + (u32)(k * 132 + s32 * 4) * 4, src);
        }
        #pragma unroll
        for (int e = 0; e < 8; e++) {
            int id = tid + 256 * e;
            int k = id & 15, r = id >> 4;
            const float* src = A + (size_t)(mBase + r) * ldA + c * BKC + k;
            CP4(asb[s] + (u32)(k * 132 + r) * 4, src);
        }
        CPCOMMIT();
    };

    issue(0); issue(1);
    CPWAIT1(); __syncthreads();

    #pragma unroll 1
    for (int c = 0; c < NC; c++) {
        if (c + 2 < NC) issue(c + 2);
        const float* Ap = Asm + (c % 3) * BST;
        const float* Bp = Bsm + (c % 3) * BST;
        #pragma unroll
        for (int k = 0; k < BKC; k++) {
            float4 a0 = *(const float4*)(Ap + k * 132 + ty * 8);
            float4 a1 = *(const float4*)(Ap + k * 132 + ty * 8 + 4);
            float4 b0 = *(const float4*)(Bp + k * 132 + tx * 8);
            float4 b1 = *(const float4*)(Bp + k * 132 + tx * 8 + 4);
            u64 w[4] = { pack2(b0.x, b0.y), pack2(b0.z, b0.w),
                         pack2(b1.x, b1.y), pack2(b1.z, b1.w) };
            float am[8] = { a0.x, a0.y, a0.z, a0.w, a1.x, a1.y, a1.z, a1.w };
            #pragma unroll
            for (int m = 0; m < 8; m++) {
                u64 aa = pack2(am[m], am[m]);
                #pragma unroll
                for (int np = 0; np < 4; np++) fma2(acc[m][np], w[np], aa);
            }
        }
        if (c + 2 < NC) { CPWAIT1(); } else { CPWAIT0(); }
        __syncthreads();
    }
}

// Writes gx transposed: gx[(t*4+g)][h][b] = acc + bias
__device__ __forceinline__ void bulk_epilogue(
    u64 acc[8][4], const float* __restrict__ bias, int mBase, int nBase)
{
    const int tid = threadIdx.x;
    const int tx = tid & 15, ty = tid >> 4;
    const int t = mBase >> 8;
    const int b0 = (mBase & 255) + ty * 8;

    float4 bb0 = *(const float4*)(bias + nBase + tx * 8);
    float4 bb1 = *(const float4*)(bias + nBase + tx * 8 + 4);
    float bcol[8] = { bb0.x, bb0.y, bb0.z, bb0.w, bb1.x, bb1.y, bb1.z, bb1.w };

    float f[8][8];
    #pragma unroll
    for (int m = 0; m < 8; m++) {
        #pragma unroll
        for (int np = 0; np < 4; np++) {
            float lo, hi;
            unpack2(acc[m][np], lo, hi);
            f[m][2 * np]     = lo + bcol[2 * np];
            f[m][2 * np + 1] = hi + bcol[2 * np + 1];
        }
    }
    #pragma unroll
    for (int nn = 0; nn < 8; nn++) {
        int n = nBase + tx * 8 + nn;
        int g = n >> 9, h = n & 511;
        float* dst = g_gx + (((size_t)(t * 4 + g)) * H_DIM + h) * B_DIM + b0;
        float4 v0 = make_float4(f[0][nn], f[1][nn], f[2][nn], f[3][nn]);
        float4 v1 = make_float4(f[4][nn], f[5][nn], f[6][nn], f[7][nn]);
        *(float4*)dst = v0;
        *(float4*)(dst + 4) = v1;
    }
}

// layer0: gx = bias0 + x@Wih0 + b@Wbh0
__global__ void __launch_bounds__(256, 2) bulk0_kernel(
    const float* __restrict__ x, const float* __restrict__ br,
    const float* __restrict__ Wih, const float* __restrict__ Wbh,
    const float* __restrict__ bias)
{
    extern __shared__ __align__(16) float sm[];
    float* Asm = sm;
    float* Bsm = sm + 3 * BST;
    const int nBase = blockIdx.x * 128;
    const int mBase = blockIdx.y * 128;

    u64 acc[8][4] = {};
    bulk_seg<IN_DIM / BKC>(acc, x, IN_DIM, Wih, mBase, nBase, Asm, Bsm);
    bulk_seg<BR_DIM / BKC>(acc, br, BR_DIM, Wbh, mBase, nBase, Asm, Bsm);
    bulk_epilogue(acc, bias, mBase, nBase);
}

// layer1: gx = bias1 + hs0@Wih1, with hs0 stored transposed [t][h][b]
__global__ void __launch_bounds__(256, 2) bulk1_kernel(
    const float* __restrict__ Wih, const float* __restrict__ bias)
{
    extern __shared__ __align__(16) float sm[];
    float* Asm = sm;
    float* Bsm = sm + 3 * BST;
    const int tid = threadIdx.x;
    const int nBase = blockIdx.x * 128;
    const int mBase = blockIdx.y * 128;
    const int t = mBase >> 8;
    const int bo = mBase & 255;

    u32 asb[3], bsb[3];
    #pragma unroll
    for (int s = 0; s < 3; s++) {
        asb[s] = smem_u32(Asm + s * BST);
        bsb[s] = smem_u32(Bsm + s * BST);
    }

    auto issue = [&](int c) {
        int s = c % 3;
        #pragma unroll
        for (int e = 0; e < 2; e++) {
            int id = tid + 256 * e;
            int k = id >> 5, s32 = id & 31;
            const float* src = Wih + (size_t)(c * BKC + k) * G_DIM + nBase + s32 * 4;
            CP16(bsb[s] + (u32)(k * 132 + s32 * 4) * 4, src);
        }
        // A from g_hs0[t][k][b] : k-major rows, CP16, no transpose
        #pragma unroll
        for (int e = 0; e < 2; e++) {
            int id = tid + 256 * e;
            int k = id >> 5, seg = id & 31;
            const float* src = g_hs0 + ((size_t)t * H_DIM + c * BKC + k) * B_DIM + bo + seg * 4;
            CP16(asb[s] + (u32)(k * 132 + seg * 4) * 4, src);
        }
        CPCOMMIT();
    };

    u64 acc[8][4] = {};
    issue(0); issue(1);
    CPWAIT1(); __syncthreads();

    const int tx = tid & 15, ty = tid >> 4;
    #pragma unroll 1
    for (int c = 0; c < H_DIM / BKC; c++) {
        if (c + 2 < H_DIM / BKC) issue(c + 2);
        const float* Ap = Asm + (c % 3) * BST;
        const float* Bp = Bsm + (c % 3) * BST;
        #pragma unroll
        for (int k = 0; k < BKC; k++) {
            float4 a0 = *(const float4*)(Ap + k * 132 + ty * 8);
            float4 a1 = *(const float4*)(Ap + k * 132 + ty * 8 + 4);
            float4 b0 = *(const float4*)(Bp + k * 132 + tx * 8);
            float4 b1 = *(const float4*)(Bp + k * 132 + tx * 8 + 4);
            u64 w[4] = { pack2(b0.x, b0.y), pack2(b0.z, b0.w),
                         pack2(b1.x, b1.y), pack2(b1.z, b1.w) };
            float am[8] = { a0.x, a0.y, a0.z, a0.w, a1.x, a1.y, a1.z, a1.w };
            #pragma unroll
            for (int m = 0; m < 8; m++) {
                u64 aa = pack2(am[m], am[m]);
                #pragma unroll
                for (int np = 0; np < 4; np++) fma2(acc[m][np], w[np], aa);
            }
        }
        if (c + 2 < H_DIM / BKC) { CPWAIT1(); } else { CPWAIT0(); }
        __syncthreads();
    }
    bulk_epilogue(acc, bias, mBase, nBase);
}

// =====================================================================
// RECURRENT persistent kernel. Grid: 32 h-CTAs (16 h, all 4 gates) x
// 4 b-CTAs (64 b). 128 threads. Warp w owns b slice [bt0+16w,+16);
// lane (bl=lane&7, hl=lane>>3) owns 2b x 4h x 4g = 32 cells.
// Per k: 1 LDS.64 (a, 8 distinct addrs) + 4 LDS.128 (w, 4 distinct,
// conflict-free via [k][g][hl][4] layout) + 16 FFMA2  -> 20 wf/SM/k vs
// 32 FMA cyc/k: FMA-bound with crossbar slack.
// W persistent in smem (128 KB). A streamed [k][b] via CP16, 4 chunks
// of 128k, 2-stage pipeline. gx LDGs at step top, consumed after GEMM.
// =====================================================================
#define RKC 128
#define RAST (RKC * 64)          // A stage floats (32 KB)
#define RW_FLOATS (H_DIM * 64)   // 32768 floats = 128 KB, [k][g][hl][4]

__global__ void __launch_bounds__(128, 1) recur_kernel(
    int layer, const float* __restrict__ Whh, float* __restrict__ out)
{
    extern __shared__ __align__(16) float sm[];
    float* Wsm = sm;                    // [k512][g4][hl4][4]
    float* Asm = sm + RW_FLOATS;        // 2 stages of [k128][64]

    const int tid = threadIdx.x;
    const int w = tid >> 5;
    const int lane = tid & 31;
    const int bl = lane & 7;
    const int hl = lane >> 3;           // 0..3
    const int ht0 = blockIdx.x * 16;    // gridDim.x = 32
    const int bt0 = blockIdx.y * 64;    // gridDim.y = 4
    const int col = blockIdx.y;
    const int myIdx = blockIdx.x;

    const int bofs = w * 16 + 2 * bl;   // local b offset (2 consecutive b)
    const int b0 = bt0 + bofs;
    const int h0 = ht0 + 4 * hl;        // 4 consecutive h

    u32 wsb = smem_u32(Wsm);
    u32 asb[2] = { smem_u32(Asm), smem_u32(Asm + RAST) };

    // ---- load W once, repacked: dst[k][g][hl][0..3] <- Whh[k][g*512+ht0+4*hl+{0..3}]
    // 512k * 4g * 4hl CP16 = 8192 / 128 threads = 64 each
    #pragma unroll 8
    for (int e = 0; e < 64; e++) {
        int id = tid + 128 * e;          // 0..8191
        int k = id >> 4;
        int q = id & 15;                 // g = q>>2, hq = q&3
        int qg = q >> 2, qh = q & 3;
        const float* src = Whh + (size_t)k * G_DIM + qg * H_DIM + ht0 + qh * 4;
        CP16(wsb + (u32)(k * 64 + qg * 16 + qh * 4) * 4, src);
    }
    CPCOMMIT(); CPWAIT0(); __syncthreads();

    float cst[2][4] = {};                // [b][h]
    float hfin[2][4] = {};

    for (int t = 0; t < S_LEN; t++) {
        const float* Asrc = (layer == 0)
            ? g_hs0 + (size_t)(t - 1) * H_DIM * B_DIM
            : g_h1t[t & 1];

        auto issueA = [&](int c) {
            int s = c & 1;
            // 128k x 64b floats = 32KB = 2048 CP16 / 128 threads = 16 each
            #pragma unroll
            for (int e = 0; e < 16; e++) {
                int id = tid + 128 * e;
                int k = id >> 4, seg = id & 15;
                const float* src = Asrc + (size_t)(c * RKC + k) * B_DIM + bt0 + seg * 4;
                CP16(asb[s] + (u32)(k * 64 + seg * 4) * 4, src);
            }
            CPCOMMIT();
        };

        if (t > 0) issueA(0);

        // ---- gx LDGs issued now, consumed only after the GEMM ----
        // gxp[g][hh] = float2 over (b0, b0+1) for h = h0 + hh
        float2 gxp[4][4];
        const float* gxb = g_gx + (size_t)t * 4 * H_DIM * B_DIM;
        #pragma unroll
        for (int g = 0; g < 4; g++) {
            #pragma unroll
            for (int hh = 0; hh < 4; hh++) {
                gxp[g][hh] = *(const float2*)(
                    gxb + ((size_t)g * H_DIM + h0 + hh) * B_DIM + b0);
            }
        }

        u64 acc[2][4][2] = {};  // [b][g][hpair], pair over (h+0,h+1)/(h+2,h+3)

        if (t > 0) {
            #pragma unroll 1
            for (int c = 0; c < 4; c++) {
                if (c + 1 < 4) issueA(c + 1);
                if (c + 1 < 4) { CPWAIT1(); } else { CPWAIT0(); }
                __syncthreads();
                const float* Ap = Asm + (c & 1) * RAST;
                const float* Wp = Wsm + c * (RKC * 64);
                #pragma unroll 8
                for (int k = 0; k < RKC; k++) {
                    float2 af = *(const float2*)(Ap + k * 64 + bofs);
                    u64 aa0 = pack2(af.x, af.x);
                    u64 aa1 = pack2(af.y, af.y);
                    #pragma unroll
                    for (int g = 0; g < 4; g++) {
                        ulonglong2 wv = *(const ulonglong2*)(Wp + k * 64 + g * 16 + hl * 4);
                        fma2(acc[0][g][0], wv.x, aa0);
                        fma2(acc[0][g][1], wv.y, aa0);
                        fma2(acc[1][g][0], wv.x, aa1);
                        fma2(acc[1][g][1], wv.y, aa1);
                    }
                }
                __syncthreads();
            }
        }

        // ---- add input-side preacts (gx) ----
        #pragma unroll
        for (int g = 0; g < 4; g++) {
            #pragma unroll
            for (int b = 0; b < 2; b++) {
                float v0 = (b == 0) ? gxp[g][0].x : gxp[g][0].y;
                float v1 = (b == 0) ? gxp[g][1].x : gxp[g][1].y;
                float v2 = (b == 0) ? gxp[g][2].x : gxp[g][2].y;
                float v3 = (b == 0) ? gxp[g][3].x : gxp[g][3].y;
                add2(acc[b][g][0], pack2(v0, v1));
                add2(acc[b][g][1], pack2(v2, v3));
            }
        }

        // ---- gates (cells: 2b x 4h) ----
        #pragma unroll
        for (int b = 0; b < 2; b++) {
            #pragma unroll
            for (int p = 0; p < 2; p++) {
                float i0, i1, f0, f1, q0, q1, o0, o1;
                unpack2(acc[b][0][p], i0, i1);
                unpack2(acc[b][1][p], f0, f1);
                unpack2(acc[b][2][p], q0, q1);
                unpack2(acc[b][3][p], o0, o1);
                float c0 = fast_sigmoid(f0) * cst[b][2 * p + 0] + fast_sigmoid(i0) * fast_tanh(q0);
                float c1 = fast_sigmoid(f1) * cst[b][2 * p + 1] + fast_sigmoid(i1) * fast_tanh(q1);
                cst[b][2 * p + 0] = c0; cst[b][2 * p + 1] = c1;
                hfin[b][2 * p + 0] = fast_sigmoid(o0) * fast_tanh(c0);
                hfin[b][2 * p + 1] = fast_sigmoid(o1) * fast_tanh(c1);
            }
        }

        // ---- stores ----
        if (layer == 0) {
            #pragma unroll
            for (int hh = 0; hh < 4; hh++) {
                *(float2*)(g_hs0 + ((size_t)t * H_DIM + h0 + hh) * B_DIM + b0) =
                    make_float2(hfin[0][hh], hfin[1][hh]);
            }
        } else {
            float* hb = g_h1t[(t + 1) & 1];
            #pragma unroll
            for (int hh = 0; hh < 4; hh++) {
                *(float2*)(hb + ((size_t)(h0 + hh)) * B_DIM + b0) =
                    make_float2(hfin[0][hh], hfin[1][hh]);
            }
            #pragma unroll
            for (int b = 0; b < 2; b++) {
                *(float4*)(out + ((size_t)t * B_DIM + b0 + b) * H_DIM + h0) =
                    make_float4(hfin[b][0], hfin[b][1], hfin[b][2], hfin[b][3]);
            }
        }

        gsync_col(col, myIdx, (layer == 0 ? 0u : (unsigned)S_LEN) + (unsigned)t + 1u);
    }

    // ---- finals: h_n, c_n ----
    const size_t base = (size_t)S_LEN * B_DIM * H_DIM;
    const size_t BH = (size_t)B_DIM * H_DIM;
    #pragma unroll
    for (int b = 0; b < 2; b++) {
        size_t row = (size_t)(b0 + b) * H_DIM + h0;
        *(float4*)(out + base + (size_t)layer * BH + row) =
            make_float4(hfin[b][0], hfin[b][1], hfin[b][2], hfin[b][3]);
        *(float4*)(out + base + (2 + (size_t)layer) * BH + row) =
            make_float4(cst[b][0], cst[b][1], cst[b][2], cst[b][3]);
    }
}

// =====================================================================
extern "C" void kernel_launch(void* const* d_in, const int* in_sizes, int n_in,
                              void* d_out, int out_size)
{
    const float* x    = (const float*)d_in[0];  // [S, B, IN]
    const float* br   = (const float*)d_in[1];  // [S, B, BR]
    const float* Wih0 = (const float*)d_in[2];  // [IN, 4H]
    const float* Wbh0 = (const float*)d_in[3];  // [BR, 4H]
    const float* Whh0 = (const float*)d_in[4];  // [H, 4H]
    const float* b0   = (const float*)d_in[5];  // [4H]
    const float* Wih1 = (const float*)d_in[6];  // [H, 4H]
    const float* Whh1 = (const float*)d_in[7];  // [H, 4H]
    const float* b1   = (const float*)d_in[8];  // [4H]
    float* out = (float*)d_out;

    const int bulk_smem  = 3 * BST * 2 * sizeof(float);            // 50688
    const int recur_smem = (RW_FLOATS + 2 * RAST) * sizeof(float); // 196608

    cudaFuncSetAttribute(bulk0_kernel, cudaFuncAttributeMaxDynamicSharedMemorySize, bulk_smem);
    cudaFuncSetAttribute(bulk1_kernel, cudaFuncAttributeMaxDynamicSharedMemorySize, bulk_smem);
    cudaFuncSetAttribute(recur_kernel, cudaFuncAttributeMaxDynamicSharedMemorySize, recur_smem);

    init_kernel<<<1, 128>>>();

    dim3 bulk_grid(G_DIM / 128, M_DIM / 128);  // (16, 1024)
    dim3 rec_grid(H_DIM / 16, B_DIM / 64);     // (32, 4) = 128 CTAs

    bulk0_kernel<<<bulk_grid, 256, bulk_smem>>>(x, br, Wih0, Wbh0, b0);
    recur_kernel<<<rec_grid, 128, recur_smem>>>(0, Whh0, out);
    bulk1_kernel<<<bulk_grid, 256, bulk_smem>>>(Wih1, b1);
    recur_kernel<<<rec_grid, 128, recur_smem>>>(1, Whh1, out);
}